// round 7
// baseline (speedup 1.0000x reference)
#include <cuda_runtime.h>

#define BSZ 32
#define CCH 256
#define NPX 4096
#define REGF 0.01f

#define TCR 32            // c-rows per block tile
#define TDR 16            // d-rows per block tile
#define TNN 64            // n per block tile
#define KB  4             // b per chunk
#define NCHUNK (BSZ / KB) // 8
#define CPART (KB * TCR * TNN)          // 8192 floats
#define DPART (KB * TDR * TNN)          // 4096 floats
#define BUF   (CPART + DPART)           // 12288 floats
#define NBUF  4                          // 192 KB total

typedef unsigned long long ull;

// packed fp32x2 FMA (2 FMAs/instr); ptxas never emits from C++.
__device__ __forceinline__ void ffma2(ull& acc, ull a, ull b) {
    asm("fma.rn.f32x2 %0, %1, %2, %0;" : "+l"(acc) : "l"(a), "l"(b));
}
__device__ __forceinline__ unsigned smem_u32(const void* p) {
    return (unsigned)__cvta_generic_to_shared(p);
}
__device__ __forceinline__ void cp16(unsigned s, const float* g) {
    asm volatile("cp.async.cg.shared.global [%0], [%1], 16;" :: "r"(s), "l"(g));
}
#define CP_COMMIT() asm volatile("cp.async.commit_group;" ::: "memory")
#define CP_WAIT2()  asm volatile("cp.async.wait_group 2;" ::: "memory")

// ---------------------------------------------------------------------------
// Kernel 1: mean over batch. x: [B, C, N], mean: [C, N].
// ---------------------------------------------------------------------------
__global__ void mvg_mean_kernel(const float* __restrict__ x,
                                float* __restrict__ mean) {
    int idx = blockIdx.x * blockDim.x + threadIdx.x;
    const float4* x4 = (const float4*)x;
    float4 s = make_float4(0.f, 0.f, 0.f, 0.f);
    const int stride = CCH * NPX / 4;
#pragma unroll
    for (int b = 0; b < BSZ; b++) {
        float4 v = x4[b * stride + idx];
        s.x += v.x; s.y += v.y; s.z += v.z; s.w += v.w;
    }
    const float inv = 1.0f / BSZ;
    s.x *= inv; s.y *= inv; s.z *= inv; s.w *= inv;
    ((float4*)mean)[idx] = s;
}

// ---------------------------------------------------------------------------
// Kernel 2: cov[c,d,n] = (sum_b x_c x_d - B m_c m_d)/(B-1) + REG*(c==d)
// Block tile: 32c x 16d x 64n.  (ci, dj) with dj >= 2*ci; mirrored writes
// fill the lower triangle.  512 threads = 32 n-lanes x 16 (c,d)-warps;
// warp-uniform (c,d) => all LDS are contiguous 256B, zero conflicts.
// Microtile 8c x 4d x 2n packed f32x2 (64 acc regs -> 16 warps/SM).
// Staging: cp.async, 4 buffers, 3 chunks ahead, ONE sync per chunk.
// ---------------------------------------------------------------------------
__global__ __launch_bounds__(512, 1)
void mvg_cov_kernel(const float* __restrict__ x,
                    const float* __restrict__ mean,
                    float* __restrict__ cov) {
    // decode (ci, dj): ci in [0,8), dj in [2*ci, 16)
    int rem = blockIdx.x;
    int ci = 0;
    while (rem >= 16 - 2 * ci) { rem -= 16 - 2 * ci; ci++; }
    const int dj = 2 * ci + rem;
    const bool sub = (dj >> 1) == ci;    // d-rows subset of c-rows
    const int n0 = blockIdx.y * TNN;

    extern __shared__ float sm[];        // NBUF * BUF floats

    const int tid = threadIdx.x;
    const int tn  = tid & 31;            // n-pair lane (2 n per thread)
    const int w   = tid >> 5;
    const int tc  = w & 3;               // 8 c-rows each
    const int td  = w >> 2;              // 4 d-rows each

    // ---- stage chunk ck (b-range [ck*KB, +KB)) into buffer ck%NBUF ----
    auto stage = [&](int ck) {
        float* dst = sm + (ck & (NBUF - 1)) * BUF;
        const int kb = ck * KB;
        // c-part: 4 x (32 rows x 16 float4); bb == r
#pragma unroll
        for (int r = 0; r < 4; r++) {
            int row = tid >> 4;
            int nn4 = (tid & 15) << 2;
            cp16(smem_u32(dst + (r * TCR + row) * TNN + nn4),
                 &x[((size_t)(kb + r) * CCH + ci * TCR + row) * NPX + n0 + nn4]);
        }
        if (!sub) {
            // d-part: 2 x (2bb x 16 rows x 16 float4)
#pragma unroll
            for (int r = 0; r < 2; r++) {
                int bb  = 2 * r + (tid >> 8);
                int row = (tid >> 4) & 15;
                int nn4 = (tid & 15) << 2;
                cp16(smem_u32(dst + CPART + (bb * TDR + row) * TNN + nn4),
                     &x[((size_t)(kb + bb) * CCH + dj * TDR + row) * NPX + n0 + nn4]);
            }
        }
        CP_COMMIT();
    };

    ull acc[8][4];
#pragma unroll
    for (int i = 0; i < 8; i++)
#pragma unroll
        for (int j = 0; j < 4; j++) acc[i][j] = 0ull;

    const int bstr = sub ? TCR : TDR;    // d row-stride inside its region
    const int dofs = sub ? (dj & 1) * TDR * TNN : CPART;

    auto compute = [&](int ck) {
        const float* pc = sm + (ck & (NBUF - 1)) * BUF;
        const float* pa = pc + (tc * 8) * TNN + 2 * tn;
        const float* pb = pc + dofs + (td * 4) * TNN + 2 * tn;
#pragma unroll
        for (int bb = 0; bb < KB; bb++) {
            ull av[8], bv[4];
#pragma unroll
            for (int i = 0; i < 8; i++)
                av[i] = *(const ull*)&pa[(bb * TCR + i) * TNN];
#pragma unroll
            for (int j = 0; j < 4; j++)
                bv[j] = *(const ull*)&pb[(bb * bstr + j) * TNN];
#pragma unroll
            for (int i = 0; i < 8; i++)
#pragma unroll
                for (int j = 0; j < 4; j++)
                    ffma2(acc[i][j], av[i], bv[j]);
        }
    };

    // ---- pipeline: 4 buffers, 3 chunks in flight, one sync per chunk ----
    stage(0); stage(1); stage(2);
#pragma unroll
    for (int ck = 0; ck < NCHUNK; ck++) {
        CP_WAIT2();                 // group ck complete (ck+3 issued, wait<=2)
        __syncthreads();
        compute(ck);
        if (ck + 3 < NCHUNK) stage(ck + 3);
        else CP_COMMIT();           // empty group keeps wait count aligned
    }

    // ---- epilogue: mean correction, scale, reg, write + mirror ----
    const float scale = 1.0f / (BSZ - 1);
    const int n = n0 + 2 * tn;
    float2 md[4];
#pragma unroll
    for (int j = 0; j < 4; j++)
        md[j] = *(const float2*)&mean[(size_t)(dj * TDR + td * 4 + j) * NPX + n];
#pragma unroll
    for (int i = 0; i < 8; i++) {
        const int c = ci * TCR + tc * 8 + i;
        float2 mc = *(const float2*)&mean[(size_t)c * NPX + n];
#pragma unroll
        for (int j = 0; j < 4; j++) {
            const int d = dj * TDR + td * 4 + j;
            ull a = acc[i][j];
            float lo = __uint_as_float((unsigned)(a & 0xffffffffull));
            float hi = __uint_as_float((unsigned)(a >> 32));
            lo = (lo - (float)BSZ * mc.x * md[j].x) * scale;
            hi = (hi - (float)BSZ * mc.y * md[j].y) * scale;
            if (c == d) { lo += REGF; hi += REGF; }
            float2 o = make_float2(lo, hi);
            __stcs((float2*)&cov[((size_t)c * CCH + d) * NPX + n], o);
            __stcs((float2*)&cov[((size_t)d * CCH + c) * NPX + n], o);
        }
    }
}

// ---------------------------------------------------------------------------
extern "C" void kernel_launch(void* const* d_in, const int* in_sizes, int n_in,
                              void* d_out, int out_size) {
    const float* x = (const float*)d_in[0];
    float* out  = (float*)d_out;
    float* mean = out;                          // [C, N]
    float* cov  = out + (size_t)CCH * NPX;      // [C, C, N]

    mvg_mean_kernel<<<(CCH * NPX / 4) / 256, 256>>>(x, mean);

    static bool attr_set = false;
    const int smem_bytes = NBUF * BUF * 4;      // 196,608 B
    if (!attr_set) {
        cudaFuncSetAttribute(mvg_cov_kernel,
                             cudaFuncAttributeMaxDynamicSharedMemorySize,
                             smem_bytes);
        attr_set = true;
    }
    dim3 grid(72, NPX / TNN);                   // (72, 64)
    mvg_cov_kernel<<<grid, 512, smem_bytes>>>(x, mean, cov);
}